// round 6
// baseline (speedup 1.0000x reference)
#include <cuda_runtime.h>
#include <cuda_bf16.h>
#include <cstdint>

typedef uint32_t u32;

#define S_LEN 2048
#define NH 16
#define DIM 64
#define BLKM 64          // T rows per CTA
#define BLKS 128         // K/V rows per j-step
#define NMB 32           // S_LEN / BLKM
#define ROWSTRIDE 3072   // 3*NH*DIM floats between consecutive s rows

#define HLQ 8192         // one [64][64] bf16 half-tile
#define HLK 16384        // one [128][64] bf16 half-tile
// smem layout
#define OFF_Q   0                      // Q split tiles (hi/lo)           16KB
#define OFF_K   (OFF_Q + 2*HLQ)        // K or V split tiles (hi/lo)      32KB
#define OFF_O2  (OFF_K + 2*HLK)        // -O2 split tiles (hi/lo)         16KB
#define OFF_STG (OFF_O2 + 2*HLQ)       // fp32 staging [128][64]          32KB
#define SMEM_TOTAL (OFF_STG + 32768)   // 98304 B -> 2 CTAs/SM
#define RED_OFF OFF_K                  // f32 cross-warp reduce staging (aliases KV buffer)

// ------------------------------------------------------------------ helpers
__device__ __forceinline__ u32 smem_u32(const void* p) {
    u32 a; asm("{ .reg .u64 t; cvta.to.shared.u64 t, %1; cvt.u32.u64 %0, t; }"
               : "=r"(a) : "l"(p));
    return a;
}
__device__ __forceinline__ u32 off64(int r, int cb) { return (u32)(r * 128 + (cb ^ ((r & 7) << 4))); }

__device__ __forceinline__ void ldsm4(u32 a, u32& r0, u32& r1, u32& r2, u32& r3) {
    asm volatile("ldmatrix.sync.aligned.m8n8.x4.shared.b16 {%0,%1,%2,%3}, [%4];"
        : "=r"(r0), "=r"(r1), "=r"(r2), "=r"(r3) : "r"(a));
}
__device__ __forceinline__ void ldsm4t(u32 a, u32& r0, u32& r1, u32& r2, u32& r3) {
    asm volatile("ldmatrix.sync.aligned.m8n8.x4.trans.shared.b16 {%0,%1,%2,%3}, [%4];"
        : "=r"(r0), "=r"(r1), "=r"(r2), "=r"(r3) : "r"(a));
}
__device__ __forceinline__ void mma_bf16(float* c, u32 a0, u32 a1, u32 a2, u32 a3,
                                         u32 b0, u32 b1) {
    asm volatile("mma.sync.aligned.m16n8k16.row.col.f32.bf16.bf16.f32 "
        "{%0,%1,%2,%3}, {%4,%5,%6,%7}, {%8,%9}, {%0,%1,%2,%3};"
        : "+f"(c[0]), "+f"(c[1]), "+f"(c[2]), "+f"(c[3])
        : "r"(a0), "r"(a1), "r"(a2), "r"(a3), "r"(b0), "r"(b1));
}
__device__ __forceinline__ void split2(float x, __nv_bfloat16& h, __nv_bfloat16& l) {
    h = __float2bfloat16(x);
    l = __float2bfloat16(x - __bfloat162float(h));
}
__device__ __forceinline__ void split_pack(float v0, float v1, u32& hp, u32& lp) {
    __nv_bfloat16 h0, l0, h1, l1;
    split2(v0, h0, l0); split2(v1, h1, l1);
    __nv_bfloat162 hh; hh.x = h0; hh.y = h1;
    __nv_bfloat162 ll; ll.x = l0; ll.y = l1;
    hp = *reinterpret_cast<u32*>(&hh);
    lp = *reinterpret_cast<u32*>(&ll);
}

#define CP_COMMIT() asm volatile("cp.async.commit_group;" ::: "memory")
#define CP_WAIT0()  asm volatile("cp.async.wait_group 0;" ::: "memory")

// ---- issue cp.async for a 128x64 fp32 tile -> staging (128 thr, 16x16B each) ----
__device__ __forceinline__ void cpasync_tile(u32 stg, const float* src, int tid) {
#pragma unroll
    for (int it = 0; it < 16; ++it) {
        int f = tid + it * 128;
        int s = f >> 4, dq = (f & 15) << 2;
        u32 dst = stg + (u32)(s * 256 + dq * 4);
        const float* g = src + (size_t)s * ROWSTRIDE + dq;
        asm volatile("cp.async.cg.shared.global [%0], [%1], 16;" :: "r"(dst), "l"(g));
    }
    CP_COMMIT();
}

// ---- convert staged fp32 tile -> split-bf16 hi/lo swizzled tiles ----
template <int NIT, int HL>
__device__ __forceinline__ void convert_stage(char* sm, int base, int tid) {
#pragma unroll
    for (int it = 0; it < NIT; ++it) {
        int f = tid + it * 128;
        int s = f >> 4, dq = (f & 15) << 2;
        float4 v = *reinterpret_cast<const float4*>(sm + OFF_STG + s * 256 + dq * 4);
        __nv_bfloat16 h0, l0, h1, l1, h2, l2, h3, l3;
        split2(v.x, h0, l0); split2(v.y, h1, l1);
        split2(v.z, h2, l2); split2(v.w, h3, l3);
        u32 o = off64(s, dq << 1);
        __nv_bfloat162 p;
        p.x = h0; p.y = h1; *reinterpret_cast<__nv_bfloat162*>(sm + base + o)          = p;
        p.x = h2; p.y = h3; *reinterpret_cast<__nv_bfloat162*>(sm + base + o + 4)      = p;
        p.x = l0; p.y = l1; *reinterpret_cast<__nv_bfloat162*>(sm + base + HL + o)     = p;
        p.x = l2; p.y = l3; *reinterpret_cast<__nv_bfloat162*>(sm + base + HL + o + 4) = p;
    }
}

// ---- direct LDG load of Q (once per CTA) ----
__device__ __forceinline__ void load_q(char* sm, const float* src, int tid) {
#pragma unroll
    for (int it = 0; it < 8; ++it) {
        int f = tid + it * 128;
        int s = f >> 4, dq = (f & 15) << 2;
        float4 v = *reinterpret_cast<const float4*>(src + (size_t)s * ROWSTRIDE + dq);
        __nv_bfloat16 h0, l0, h1, l1, h2, l2, h3, l3;
        split2(v.x * 2.0f, h0, l0); split2(v.y * 2.0f, h1, l1);
        split2(v.z * 2.0f, h2, l2); split2(v.w * 2.0f, h3, l3);
        u32 o = off64(s, dq << 1);
        __nv_bfloat162 p;
        p.x = h0; p.y = h1; *reinterpret_cast<__nv_bfloat162*>(sm + OFF_Q + o)           = p;
        p.x = h2; p.y = h3; *reinterpret_cast<__nv_bfloat162*>(sm + OFF_Q + o + 4)       = p;
        p.x = l0; p.y = l1; *reinterpret_cast<__nv_bfloat162*>(sm + OFF_Q + HLQ + o)     = p;
        p.x = l2; p.y = l3; *reinterpret_cast<__nv_bfloat162*>(sm + OFF_Q + HLQ + o + 4) = p;
    }
}

// ---- GEMM1: acc[32x64 slice] += A[rows x 64] * (B[128x64])^T, 3-term split ----
template <int HLA, int HLB>
__device__ __forceinline__ void gemm_nT(u32 aHi, u32 bHi, float (&acc)[2][8][4],
                                        int lane, int mbase, int nbase) {
    const int arL = lane & 15, acL = (lane >> 4) << 4;
    const int brL = ((lane >> 4) << 3) + (lane & 7), bcL = ((lane >> 3) & 1) << 4;
#pragma unroll
    for (int kk = 0; kk < 4; ++kk) {
        const int kb = kk << 5;
        u32 aH[2][4], aL[2][4];
#pragma unroll
        for (int mt = 0; mt < 2; ++mt) {
            u32 ad = aHi + off64(mbase + mt * 16 + arL, kb + acL);
            ldsm4(ad,       aH[mt][0], aH[mt][1], aH[mt][2], aH[mt][3]);
            ldsm4(ad + HLA, aL[mt][0], aL[mt][1], aL[mt][2], aL[mt][3]);
        }
#pragma unroll
        for (int nt2 = 0; nt2 < 4; ++nt2) {
            u32 bd = bHi + off64(nbase + nt2 * 16 + brL, kb + bcL);
            u32 bh0, bh1, bh2, bh3, bl0, bl1, bl2, bl3;
            ldsm4(bd,       bh0, bh1, bh2, bh3);
            ldsm4(bd + HLB, bl0, bl1, bl2, bl3);
#pragma unroll
            for (int mt = 0; mt < 2; ++mt) {
                float* c0 = acc[mt][nt2 * 2];
                float* c1 = acc[mt][nt2 * 2 + 1];
                mma_bf16(c0, aH[mt][0], aH[mt][1], aH[mt][2], aH[mt][3], bh0, bh1);
                mma_bf16(c0, aH[mt][0], aH[mt][1], aH[mt][2], aH[mt][3], bl0, bl1);
                mma_bf16(c0, aL[mt][0], aL[mt][1], aL[mt][2], aL[mt][3], bh0, bh1);
                mma_bf16(c1, aH[mt][0], aH[mt][1], aH[mt][2], aH[mt][3], bh2, bh3);
                mma_bf16(c1, aH[mt][0], aH[mt][1], aH[mt][2], aH[mt][3], bl2, bl3);
                mma_bf16(c1, aL[mt][0], aL[mt][1], aL[mt][2], aL[mt][3], bh2, bh3);
            }
        }
    }
}

// ---- mask (absolute row/col) + in-register split into A-operand packs ----
__device__ __forceinline__ void mask_pack(float (&acc)[2][8][4],
                                          u32 (&pH)[2][4][4], u32 (&pL)[2][4][4],
                                          int lane, int rowAbs0, int colAbs0, bool diag) {
    if (diag) {
#pragma unroll
        for (int mt = 0; mt < 2; ++mt)
#pragma unroll
            for (int nt = 0; nt < 8; ++nt) {
                int col = colAbs0 + nt * 8 + ((lane & 3) << 1);
#pragma unroll
                for (int rr = 0; rr < 2; ++rr) {
                    int row = rowAbs0 + mt * 16 + (lane >> 2) + rr * 8;
                    if (col     > row) acc[mt][nt][rr * 2 + 0] = 0.0f;
                    if (col + 1 > row) acc[mt][nt][rr * 2 + 1] = 0.0f;
                }
            }
    }
#pragma unroll
    for (int mt = 0; mt < 2; ++mt)
#pragma unroll
        for (int kk = 0; kk < 4; ++kk) {
            split_pack(acc[mt][2*kk  ][0], acc[mt][2*kk  ][1], pH[mt][kk][0], pL[mt][kk][0]);
            split_pack(acc[mt][2*kk  ][2], acc[mt][2*kk  ][3], pH[mt][kk][1], pL[mt][kk][1]);
            split_pack(acc[mt][2*kk+1][0], acc[mt][2*kk+1][1], pH[mt][kk][2], pL[mt][kk][2]);
            split_pack(acc[mt][2*kk+1][2], acc[mt][2*kk+1][3], pH[mt][kk][3], pL[mt][kk][3]);
        }
}

// ---- GEMM2: po[32x64] += S_slice(regs) * B[k-slice x 64], B via ldmatrix.trans ----
__device__ __forceinline__ void gemm2_reg(const u32 (&pH)[2][4][4], const u32 (&pL)[2][4][4],
                                          u32 bHi, float (&po)[2][8][4],
                                          int lane, int kbase) {
    const int brL = (((lane >> 3) & 1) << 3) + (lane & 7), bcL = (lane >> 4) << 4;
#pragma unroll
    for (int kk = 0; kk < 4; ++kk) {
#pragma unroll
        for (int nt2 = 0; nt2 < 4; ++nt2) {
            u32 bd = bHi + off64(kbase + kk * 16 + brL, (nt2 << 5) + bcL);
            u32 bh0, bh1, bh2, bh3, bl0, bl1, bl2, bl3;
            ldsm4t(bd,       bh0, bh1, bh2, bh3);
            ldsm4t(bd + HLK, bl0, bl1, bl2, bl3);
#pragma unroll
            for (int mt = 0; mt < 2; ++mt) {
                float* c0 = po[mt][nt2 * 2];
                float* c1 = po[mt][nt2 * 2 + 1];
                mma_bf16(c0, pH[mt][kk][0], pH[mt][kk][1], pH[mt][kk][2], pH[mt][kk][3], bh0, bh1);
                mma_bf16(c0, pH[mt][kk][0], pH[mt][kk][1], pH[mt][kk][2], pH[mt][kk][3], bl0, bl1);
                mma_bf16(c0, pL[mt][kk][0], pL[mt][kk][1], pL[mt][kk][2], pL[mt][kk][3], bh0, bh1);
                mma_bf16(c1, pH[mt][kk][0], pH[mt][kk][1], pH[mt][kk][2], pH[mt][kk][3], bh2, bh3);
                mma_bf16(c1, pH[mt][kk][0], pH[mt][kk][1], pH[mt][kk][2], pH[mt][kk][3], bl2, bl3);
                mma_bf16(c1, pL[mt][kk][0], pL[mt][kk][1], pL[mt][kk][2], pL[mt][kk][3], bh2, bh3);
            }
        }
    }
}

#define ZERO_PO(po) \
    _Pragma("unroll") for (int mt = 0; mt < 2; ++mt) \
    _Pragma("unroll") for (int nt = 0; nt < 8; ++nt) \
    _Pragma("unroll") for (int e = 0; e < 4; ++e) (po)[mt][nt][e] = 0.0f;

__global__ void __launch_bounds__(128, 2)
ttt_mma_kernel(const float* __restrict__ qkv, float* __restrict__ out) {
    extern __shared__ char sm[];
    const u32 sb = smem_u32(sm);
    const int tid = threadIdx.x, lane = tid & 31, wid = tid >> 5;
    const int wm = wid & 1, wn = wid >> 1;
    const int mbase = wm * 32, kbase = wn * 64;

    const int mb = (NMB - 1) - (int)blockIdx.y;     // heavy T-blocks first
    const int bh = blockIdx.x, b = bh >> 4, h = bh & 15;
    const float* base = qkv + (size_t)b * S_LEN * ROWSTRIDE + h * DIM;
    const float* gQ = base;
    const float* gK = base + NH * DIM;
    const float* gV = base + 2 * NH * DIM;
    const int t0 = mb * BLKM;
    const int nK = (mb >> 1) + 1;                   // 128-row K blocks needed
    const bool evenMb = (mb & 1) == 0;

    // kick K0 into staging, then load Q (Q's LDG latency overlaps K0's)
    cpasync_tile(sb + OFF_STG, gK, tid);
    load_q(sm, gQ + (size_t)t0 * ROWSTRIDE, tid);

    // ================= pass 1: po = partial of tril(2Q K^T) K  (= 2*O2) =================
    float po[2][8][4];
    ZERO_PO(po);
    for (int j = 0; j < nK; ++j) {
        CP_WAIT0(); __syncthreads();               // stage has K_j; prev gemm2 done with KV
        convert_stage<16, HLK>(sm, OFF_K, tid);    // K_j -> split bf16
        __syncthreads();                           // KV visible; stage free
        int jn = (j + 1 < nK) ? j + 1 : 0;         // last iter prefetches K0 for pass 2
        cpasync_tile(sb + OFF_STG, gK + (size_t)jn * BLKS * ROWSTRIDE, tid);

        const bool active = !(j == nK - 1 && evenMb && wn == 1);  // dead diagonal half
        if (active) {
            float acc1[2][8][4];
            ZERO_PO(acc1);
            gemm_nT<HLQ, HLK>(sb + OFF_Q, sb + OFF_K, acc1, lane, mbase, kbase);
            u32 pH[2][4][4], pL[2][4][4];
            mask_pack(acc1, pH, pL, lane, t0 + mbase, j * BLKS + kbase, j == nK - 1);
            gemm2_reg(pH, pL, sb + OFF_K, po, lane, kbase);
        }
    }

    // cross-warp reduce po (wn pairs) -> -O2 split tiles in sO2 (staging aliases KV buf)
    __syncthreads();
    if (wn == 1) {
#pragma unroll
        for (int mt = 0; mt < 2; ++mt)
#pragma unroll
            for (int nt = 0; nt < 8; ++nt)
#pragma unroll
                for (int rr = 0; rr < 2; ++rr) {
                    int rl = mt * 16 + (lane >> 2) + rr * 8;
                    int col = nt * 8 + ((lane & 3) << 1);
                    float2 v = make_float2(po[mt][nt][rr * 2], po[mt][nt][rr * 2 + 1]);
                    *reinterpret_cast<float2*>(sm + RED_OFF + wm * 8192 + rl * 256 + col * 4) = v;
                }
    }
    __syncthreads();
    if (wn == 0) {
#pragma unroll
        for (int mt = 0; mt < 2; ++mt)
#pragma unroll
            for (int nt = 0; nt < 8; ++nt)
#pragma unroll
                for (int rr = 0; rr < 2; ++rr) {
                    int rl = mt * 16 + (lane >> 2) + rr * 8;
                    int col = nt * 8 + ((lane & 3) << 1);
                    float2 p = *reinterpret_cast<float2*>(sm + RED_OFF + wm * 8192 + rl * 256 + col * 4);
                    float v0 = -0.5f * (po[mt][nt][rr * 2]     + p.x);
                    float v1 = -0.5f * (po[mt][nt][rr * 2 + 1] + p.y);
                    __nv_bfloat16 h0, l0, h1, l1;
                    split2(v0, h0, l0); split2(v1, h1, l1);
                    u32 o = off64(mbase + rl, col << 1);
                    __nv_bfloat162 pk;
                    pk.x = h0; pk.y = h1; *reinterpret_cast<__nv_bfloat162*>(sm + OFF_O2 + o)       = pk;
                    pk.x = l0; pk.y = l1; *reinterpret_cast<__nv_bfloat162*>(sm + OFF_O2 + HLQ + o) = pk;
                }
    }

    // ===== pass 2: po = partial of tril(2Q K^T + (-O2) K^T) V = (2A1 - A2) V =====
    // KV bf16 buffer holds K during gemm1, then is overwritten with V for gemm2.
    ZERO_PO(po);
    for (int j = 0; j < nK; ++j) {
        CP_WAIT0(); __syncthreads();               // stage has K_j; reduce/gemm2 done with KV
        convert_stage<16, HLK>(sm, OFF_K, tid);    // K_j -> split bf16
        __syncthreads();
        cpasync_tile(sb + OFF_STG, gV + (size_t)j * BLKS * ROWSTRIDE, tid);   // V_j

        const bool active = !(j == nK - 1 && evenMb && wn == 1);
        float acc1[2][8][4];
        if (active) {
            ZERO_PO(acc1);
            gemm_nT<HLQ, HLK>(sb + OFF_Q,  sb + OFF_K, acc1, lane, mbase, kbase);
            gemm_nT<HLQ, HLK>(sb + OFF_O2, sb + OFF_K, acc1, lane, mbase, kbase);
        }

        CP_WAIT0(); __syncthreads();               // V_j staged; all warps done with K tile
        convert_stage<16, HLK>(sm, OFF_K, tid);    // V_j -> split bf16 (overwrites K)
        __syncthreads();
        int jn = (j + 1 < nK) ? j + 1 : 0;
        cpasync_tile(sb + OFF_STG, gK + (size_t)jn * BLKS * ROWSTRIDE, tid);  // K_{j+1}

        if (active) {
            u32 pH[2][4][4], pL[2][4][4];
            mask_pack(acc1, pH, pL, lane, t0 + mbase, j * BLKS + kbase, j == nK - 1);
            gemm2_reg(pH, pL, sb + OFF_K, po, lane, kbase);
        }
    }

    // cross-warp reduce po -> final out
    __syncthreads();
    if (wn == 1) {
#pragma unroll
        for (int mt = 0; mt < 2; ++mt)
#pragma unroll
            for (int nt = 0; nt < 8; ++nt)
#pragma unroll
                for (int rr = 0; rr < 2; ++rr) {
                    int rl = mt * 16 + (lane >> 2) + rr * 8;
                    int col = nt * 8 + ((lane & 3) << 1);
                    float2 v = make_float2(po[mt][nt][rr * 2], po[mt][nt][rr * 2 + 1]);
                    *reinterpret_cast<float2*>(sm + RED_OFF + wm * 8192 + rl * 256 + col * 4) = v;
                }
    }
    __syncthreads();
    if (wn == 0) {
#pragma unroll
        for (int mt = 0; mt < 2; ++mt)
#pragma unroll
            for (int nt = 0; nt < 8; ++nt)
#pragma unroll
                for (int rr = 0; rr < 2; ++rr) {
                    int rl = mt * 16 + (lane >> 2) + rr * 8;
                    int col = nt * 8 + ((lane & 3) << 1);
                    float2 p = *reinterpret_cast<float2*>(sm + RED_OFF + wm * 8192 + rl * 256 + col * 4);
                    float2 v = make_float2(po[mt][nt][rr * 2] + p.x,
                                           po[mt][nt][rr * 2 + 1] + p.y);
                    size_t off = (((size_t)b * S_LEN + t0 + mbase + rl) * NH + h) * DIM + col;
                    *reinterpret_cast<float2*>(out + off) = v;
                }
    }
}

extern "C" void kernel_launch(void* const* d_in, const int* in_sizes, int n_in,
                              void* d_out, int out_size) {
    const float* qkv = (const float*)d_in[0];
    float* out = (float*)d_out;
    cudaFuncSetAttribute(ttt_mma_kernel, cudaFuncAttributeMaxDynamicSharedMemorySize,
                         SMEM_TOTAL);
    dim3 grid(32 /*b*h*/, NMB /*reversed T-blocks*/);
    ttt_mma_kernel<<<grid, 128, SMEM_TOTAL>>>(qkv, out);
}

// round 7
// speedup vs baseline: 1.0909x; 1.0909x over previous
#include <cuda_runtime.h>
#include <cuda_bf16.h>
#include <cstdint>

typedef uint32_t u32;

#define S_LEN 2048
#define NH 16
#define DIM 64
#define BLKM 64          // T rows per CTA
#define BLKS 128         // K/V rows per j-step
#define NMB 32           // S_LEN / BLKM
#define ROWSTRIDE 3072   // 3*NH*DIM floats between consecutive s rows

#define HLQ 8192         // one [64][64] bf16 half-tile
#define HLK 16384        // one [128][64] bf16 half-tile
// smem layout (each buffer = hi tile then lo tile, off64 swizzled)
#define OFF_Q   0
#define OFF_K   (OFF_Q + 2*HLQ)        // 16384
#define OFF_V   (OFF_K + 2*HLK)        // 49152  (pass 1: fp32 K staging)
#define OFF_O2  (OFF_V + 2*HLK)        // 81920
#define SMEM_TOTAL (OFF_O2 + 2*HLQ)    // 98304 B -> 2 CTAs/SM
#define RED_OFF OFF_K                   // f32 staging for cross-warp reduce

// ------------------------------------------------------------------ helpers
__device__ __forceinline__ u32 smem_u32(const void* p) {
    u32 a; asm("{ .reg .u64 t; cvta.to.shared.u64 t, %1; cvt.u32.u64 %0, t; }"
               : "=r"(a) : "l"(p));
    return a;
}
__device__ __forceinline__ u32 off64(int r, int cb) { return (u32)(r * 128 + (cb ^ ((r & 7) << 4))); }

__device__ __forceinline__ void ldsm4(u32 a, u32& r0, u32& r1, u32& r2, u32& r3) {
    asm volatile("ldmatrix.sync.aligned.m8n8.x4.shared.b16 {%0,%1,%2,%3}, [%4];"
        : "=r"(r0), "=r"(r1), "=r"(r2), "=r"(r3) : "r"(a));
}
__device__ __forceinline__ void ldsm4t(u32 a, u32& r0, u32& r1, u32& r2, u32& r3) {
    asm volatile("ldmatrix.sync.aligned.m8n8.x4.trans.shared.b16 {%0,%1,%2,%3}, [%4];"
        : "=r"(r0), "=r"(r1), "=r"(r2), "=r"(r3) : "r"(a));
}
__device__ __forceinline__ void mma_bf16(float* c, u32 a0, u32 a1, u32 a2, u32 a3,
                                         u32 b0, u32 b1) {
    asm volatile("mma.sync.aligned.m16n8k16.row.col.f32.bf16.bf16.f32 "
        "{%0,%1,%2,%3}, {%4,%5,%6,%7}, {%8,%9}, {%0,%1,%2,%3};"
        : "+f"(c[0]), "+f"(c[1]), "+f"(c[2]), "+f"(c[3])
        : "r"(a0), "r"(a1), "r"(a2), "r"(a3), "r"(b0), "r"(b1));
}
// fast truncation split of two fp32 -> packed bf16x2 hi + lo regs
// hi = top 16 bits (PRMT pack); lo = x - hi (exact), rn-converted pair.
__device__ __forceinline__ void split_pack(float v0, float v1, u32& hp, u32& lp) {
    u32 u0 = __float_as_uint(v0), u1 = __float_as_uint(v1);
    asm("prmt.b32 %0, %1, %2, 0x7632;" : "=r"(hp) : "r"(u0), "r"(u1));
    float lo0 = v0 - __uint_as_float(u0 & 0xFFFF0000u);
    float lo1 = v1 - __uint_as_float(u1 & 0xFFFF0000u);
    asm("cvt.rn.satfinite.bf16x2.f32 %0, %1, %2;" : "=r"(lp) : "f"(lo1), "f"(lo0));
}

#define CP_COMMIT() asm volatile("cp.async.commit_group;" ::: "memory")
#define CP_WAIT0()  asm volatile("cp.async.wait_group 0;" ::: "memory")

// ---- cp.async: 128x64 fp32 tile -> fp32 staging (128 thr, 16x16B each) ----
__device__ __forceinline__ void cpasync_tile(u32 stg, const float* src, int tid) {
#pragma unroll
    for (int it = 0; it < 16; ++it) {
        int f = tid + it * 128;
        int s = f >> 4, dq = (f & 15) << 2;
        u32 dst = stg + (u32)(s * 256 + dq * 4);
        const float* g = src + (size_t)s * ROWSTRIDE + dq;
        asm volatile("cp.async.cg.shared.global [%0], [%1], 16;" :: "r"(dst), "l"(g));
    }
    CP_COMMIT();
}

// ---- convert fp32 staging (at OFF_V) -> K split-bf16 tiles ----
__device__ __forceinline__ void convert_stageK(char* sm, int tid) {
#pragma unroll
    for (int it = 0; it < 16; ++it) {
        int f = tid + it * 128;
        int s = f >> 4, dq = (f & 15) << 2;
        float4 v = *reinterpret_cast<const float4*>(sm + OFF_V + s * 256 + dq * 4);
        u32 hp0, lp0, hp1, lp1;
        split_pack(v.x, v.y, hp0, lp0);
        split_pack(v.z, v.w, hp1, lp1);
        u32 o = off64(s, dq << 1);
        *reinterpret_cast<u32*>(sm + OFF_K + o)           = hp0;
        *reinterpret_cast<u32*>(sm + OFF_K + o + 4)       = hp1;
        *reinterpret_cast<u32*>(sm + OFF_K + HLK + o)     = lp0;
        *reinterpret_cast<u32*>(sm + OFF_K + HLK + o + 4) = lp1;
    }
}

// ---- direct LDG load: R x 64 fp32 -> split-bf16 hi/lo swizzled smem ----
template <int NIT, int HL>
__device__ __forceinline__ void load_split(char* sm, int base, const float* src,
                                           float scale, int tid) {
#pragma unroll
    for (int it = 0; it < NIT; ++it) {
        int f = tid + it * 128;
        int s = f >> 4, dq = (f & 15) << 2;
        float4 v = *reinterpret_cast<const float4*>(src + (size_t)s * ROWSTRIDE + dq);
        u32 hp0, lp0, hp1, lp1;
        split_pack(v.x * scale, v.y * scale, hp0, lp0);
        split_pack(v.z * scale, v.w * scale, hp1, lp1);
        u32 o = off64(s, dq << 1);
        *reinterpret_cast<u32*>(sm + base + o)          = hp0;
        *reinterpret_cast<u32*>(sm + base + o + 4)      = hp1;
        *reinterpret_cast<u32*>(sm + base + HL + o)     = lp0;
        *reinterpret_cast<u32*>(sm + base + HL + o + 4) = lp1;
    }
}

// ---- GEMM1: acc[32x64 slice] += A[rows x 64] * (B[128x64])^T, 3-term split ----
template <int HLA, int HLB>
__device__ __forceinline__ void gemm_nT(u32 aHi, u32 bHi, float (&acc)[2][8][4],
                                        int lane, int mbase, int nbase) {
    const int arL = lane & 15, acL = (lane >> 4) << 4;
    const int brL = ((lane >> 4) << 3) + (lane & 7), bcL = ((lane >> 3) & 1) << 4;
#pragma unroll
    for (int kk = 0; kk < 4; ++kk) {
        const int kb = kk << 5;
        u32 aH[2][4], aL[2][4];
#pragma unroll
        for (int mt = 0; mt < 2; ++mt) {
            u32 ad = aHi + off64(mbase + mt * 16 + arL, kb + acL);
            ldsm4(ad,       aH[mt][0], aH[mt][1], aH[mt][2], aH[mt][3]);
            ldsm4(ad + HLA, aL[mt][0], aL[mt][1], aL[mt][2], aL[mt][3]);
        }
#pragma unroll
        for (int nt2 = 0; nt2 < 4; ++nt2) {
            u32 bd = bHi + off64(nbase + nt2 * 16 + brL, kb + bcL);
            u32 bh0, bh1, bh2, bh3, bl0, bl1, bl2, bl3;
            ldsm4(bd,       bh0, bh1, bh2, bh3);
            ldsm4(bd + HLB, bl0, bl1, bl2, bl3);
#pragma unroll
            for (int mt = 0; mt < 2; ++mt) {
                float* c0 = acc[mt][nt2 * 2];
                float* c1 = acc[mt][nt2 * 2 + 1];
                mma_bf16(c0, aH[mt][0], aH[mt][1], aH[mt][2], aH[mt][3], bh0, bh1);
                mma_bf16(c0, aH[mt][0], aH[mt][1], aH[mt][2], aH[mt][3], bl0, bl1);
                mma_bf16(c0, aL[mt][0], aL[mt][1], aL[mt][2], aL[mt][3], bh0, bh1);
                mma_bf16(c1, aH[mt][0], aH[mt][1], aH[mt][2], aH[mt][3], bh2, bh3);
                mma_bf16(c1, aH[mt][0], aH[mt][1], aH[mt][2], aH[mt][3], bl2, bl3);
                mma_bf16(c1, aL[mt][0], aL[mt][1], aL[mt][2], aL[mt][3], bh2, bh3);
            }
        }
    }
}

// ---- mask (absolute row/col) + in-register split into A-operand packs ----
__device__ __forceinline__ void mask_pack(float (&acc)[2][8][4],
                                          u32 (&pH)[2][4][4], u32 (&pL)[2][4][4],
                                          int lane, int rowAbs0, int colAbs0, bool diag) {
    if (diag) {
#pragma unroll
        for (int mt = 0; mt < 2; ++mt)
#pragma unroll
            for (int nt = 0; nt < 8; ++nt) {
                int col = colAbs0 + nt * 8 + ((lane & 3) << 1);
#pragma unroll
                for (int rr = 0; rr < 2; ++rr) {
                    int row = rowAbs0 + mt * 16 + (lane >> 2) + rr * 8;
                    if (col     > row) acc[mt][nt][rr * 2 + 0] = 0.0f;
                    if (col + 1 > row) acc[mt][nt][rr * 2 + 1] = 0.0f;
                }
            }
    }
#pragma unroll
    for (int mt = 0; mt < 2; ++mt)
#pragma unroll
        for (int kk = 0; kk < 4; ++kk) {
            split_pack(acc[mt][2*kk  ][0], acc[mt][2*kk  ][1], pH[mt][kk][0], pL[mt][kk][0]);
            split_pack(acc[mt][2*kk  ][2], acc[mt][2*kk  ][3], pH[mt][kk][1], pL[mt][kk][1]);
            split_pack(acc[mt][2*kk+1][0], acc[mt][2*kk+1][1], pH[mt][kk][2], pL[mt][kk][2]);
            split_pack(acc[mt][2*kk+1][2], acc[mt][2*kk+1][3], pH[mt][kk][3], pL[mt][kk][3]);
        }
}

// ---- GEMM2: po[32x64] += S_slice(regs) * B[k-slice x 64], B via ldmatrix.trans ----
__device__ __forceinline__ void gemm2_reg(const u32 (&pH)[2][4][4], const u32 (&pL)[2][4][4],
                                          u32 bHi, float (&po)[2][8][4],
                                          int lane, int kbase) {
    const int brL = (((lane >> 3) & 1) << 3) + (lane & 7), bcL = (lane >> 4) << 4;
#pragma unroll
    for (int kk = 0; kk < 4; ++kk) {
#pragma unroll
        for (int nt2 = 0; nt2 < 4; ++nt2) {
            u32 bd = bHi + off64(kbase + kk * 16 + brL, (nt2 << 5) + bcL);
            u32 bh0, bh1, bh2, bh3, bl0, bl1, bl2, bl3;
            ldsm4t(bd,       bh0, bh1, bh2, bh3);
            ldsm4t(bd + HLK, bl0, bl1, bl2, bl3);
#pragma unroll
            for (int mt = 0; mt < 2; ++mt) {
                float* c0 = po[mt][nt2 * 2];
                float* c1 = po[mt][nt2 * 2 + 1];
                mma_bf16(c0, pH[mt][kk][0], pH[mt][kk][1], pH[mt][kk][2], pH[mt][kk][3], bh0, bh1);
                mma_bf16(c0, pH[mt][kk][0], pH[mt][kk][1], pH[mt][kk][2], pH[mt][kk][3], bl0, bl1);
                mma_bf16(c0, pL[mt][kk][0], pL[mt][kk][1], pL[mt][kk][2], pL[mt][kk][3], bh0, bh1);
                mma_bf16(c1, pH[mt][kk][0], pH[mt][kk][1], pH[mt][kk][2], pH[mt][kk][3], bh2, bh3);
                mma_bf16(c1, pH[mt][kk][0], pH[mt][kk][1], pH[mt][kk][2], pH[mt][kk][3], bl2, bl3);
                mma_bf16(c1, pL[mt][kk][0], pL[mt][kk][1], pL[mt][kk][2], pL[mt][kk][3], bh2, bh3);
            }
        }
    }
}

#define ZERO_PO(po) \
    _Pragma("unroll") for (int mt = 0; mt < 2; ++mt) \
    _Pragma("unroll") for (int nt = 0; nt < 8; ++nt) \
    _Pragma("unroll") for (int e = 0; e < 4; ++e) (po)[mt][nt][e] = 0.0f;

__global__ void __launch_bounds__(128, 2)
ttt_mma_kernel(const float* __restrict__ qkv, float* __restrict__ out) {
    extern __shared__ char sm[];
    const u32 sb = smem_u32(sm);
    const int tid = threadIdx.x, lane = tid & 31, wid = tid >> 5;
    const int wm = wid & 1, wn = wid >> 1;
    const int mbase = wm * 32, kbase = wn * 64;

    const int mb = (NMB - 1) - (int)blockIdx.y;     // heavy T-blocks first
    const int bh = blockIdx.x, b = bh >> 4, h = bh & 15;
    const float* base = qkv + (size_t)b * S_LEN * ROWSTRIDE + h * DIM;
    const float* gQ = base;
    const float* gK = base + NH * DIM;
    const float* gV = base + 2 * NH * DIM;
    const int t0 = mb * BLKM;
    const int nK = (mb >> 1) + 1;                   // 128-row K blocks needed
    const bool evenMb = (mb & 1) == 0;

    // kick K0 -> staging (V buffer, dead in pass 1); Q LDG overlaps the copy
    cpasync_tile(sb + OFF_V, gK, tid);
    load_split<8, HLQ>(sm, OFF_Q, gQ + (size_t)t0 * ROWSTRIDE, 2.0f, tid);

    // ================= pass 1: po = partial of tril(2Q K^T) K  (= 2*O2) =================
    float po[2][8][4];
    ZERO_PO(po);
    for (int j = 0; j < nK; ++j) {
        CP_WAIT0(); __syncthreads();               // stage holds K_j; prev gemm2 done with sK
        convert_stageK(sm, tid);                   // K_j -> split bf16 (LDS, not LDG)
        __syncthreads();                           // sK visible; stage free
        if (j + 1 < nK)
            cpasync_tile(sb + OFF_V, gK + (size_t)(j + 1) * BLKS * ROWSTRIDE, tid);

        const bool active = !(j == nK - 1 && evenMb && wn == 1);  // dead diagonal half
        if (active) {
            float acc1[2][8][4];
            ZERO_PO(acc1);
            gemm_nT<HLQ, HLK>(sb + OFF_Q, sb + OFF_K, acc1, lane, mbase, kbase);
            u32 pH[2][4][4], pL[2][4][4];
            mask_pack(acc1, pH, pL, lane, t0 + mbase, j * BLKS + kbase, j == nK - 1);
            gemm2_reg(pH, pL, sb + OFF_K, po, lane, kbase);
        }
    }

    // cross-warp reduce po (wn pairs) -> -O2 split tiles in sO2
    __syncthreads();
    if (wn == 1) {
#pragma unroll
        for (int mt = 0; mt < 2; ++mt)
#pragma unroll
            for (int nt = 0; nt < 8; ++nt)
#pragma unroll
                for (int rr = 0; rr < 2; ++rr) {
                    int rl = mt * 16 + (lane >> 2) + rr * 8;
                    int col = nt * 8 + ((lane & 3) << 1);
                    float2 v = make_float2(po[mt][nt][rr * 2], po[mt][nt][rr * 2 + 1]);
                    *reinterpret_cast<float2*>(sm + RED_OFF + wm * 8192 + rl * 256 + col * 4) = v;
                }
    }
    __syncthreads();
    if (wn == 0) {
#pragma unroll
        for (int mt = 0; mt < 2; ++mt)
#pragma unroll
            for (int nt = 0; nt < 8; ++nt)
#pragma unroll
                for (int rr = 0; rr < 2; ++rr) {
                    int rl = mt * 16 + (lane >> 2) + rr * 8;
                    int col = nt * 8 + ((lane & 3) << 1);
                    float2 p = *reinterpret_cast<float2*>(sm + RED_OFF + wm * 8192 + rl * 256 + col * 4);
                    float v0 = -0.5f * (po[mt][nt][rr * 2]     + p.x);
                    float v1 = -0.5f * (po[mt][nt][rr * 2 + 1] + p.y);
                    u32 hp, lp;
                    split_pack(v0, v1, hp, lp);
                    u32 o = off64(mbase + rl, col << 1);
                    *reinterpret_cast<u32*>(sm + OFF_O2 + o)       = hp;
                    *reinterpret_cast<u32*>(sm + OFF_O2 + HLQ + o) = lp;
                }
    }

    // ===== pass 2: po = partial of tril(2Q K^T + (-O2) K^T) V = (2A1 - A2) V =====
    ZERO_PO(po);
    for (int j = 0; j < nK; ++j) {
        __syncthreads();                            // sK/sV free; sO2/staging settled
        load_split<16, HLK>(sm, OFF_K, gK + (size_t)j * BLKS * ROWSTRIDE, 1.0f, tid);
        load_split<16, HLK>(sm, OFF_V, gV + (size_t)j * BLKS * ROWSTRIDE, 1.0f, tid);
        __syncthreads();

        const bool active = !(j == nK - 1 && evenMb && wn == 1);
        if (active) {
            float acc1[2][8][4];
            ZERO_PO(acc1);
            gemm_nT<HLQ, HLK>(sb + OFF_Q,  sb + OFF_K, acc1, lane, mbase, kbase);  // 2Q K^T
            gemm_nT<HLQ, HLK>(sb + OFF_O2, sb + OFF_K, acc1, lane, mbase, kbase);  // += (-O2) K^T

            u32 pH[2][4][4], pL[2][4][4];
            mask_pack(acc1, pH, pL, lane, t0 + mbase, j * BLKS + kbase, j == nK - 1);

            gemm2_reg(pH, pL, sb + OFF_V, po, lane, kbase);                        // += S V
        }
    }

    // cross-warp reduce po -> final out
    __syncthreads();
    if (wn == 1) {
#pragma unroll
        for (int mt = 0; mt < 2; ++mt)
#pragma unroll
            for (int nt = 0; nt < 8; ++nt)
#pragma unroll
                for (int rr = 0; rr < 2; ++rr) {
                    int rl = mt * 16 + (lane >> 2) + rr * 8;
                    int col = nt * 8 + ((lane & 3) << 1);
                    float2 v = make_float2(po[mt][nt][rr * 2], po[mt][nt][rr * 2 + 1]);
                    *reinterpret_cast<float2*>(sm + RED_OFF + wm * 8192 + rl * 256 + col * 4) = v;
                }
    }
    __syncthreads();
    if (wn == 0) {
#pragma unroll
        for (int mt = 0; mt < 2; ++mt)
#pragma unroll
            for (int nt = 0; nt < 8; ++nt)
#pragma unroll
                for (int rr = 0; rr < 2; ++rr) {
                    int rl = mt * 16 + (lane >> 2) + rr * 8;
                    int col = nt * 8 + ((lane & 3) << 1);
                    float2 p = *reinterpret_cast<float2*>(sm + RED_OFF + wm * 8192 + rl * 256 + col * 4);
                    float2 v = make_float2(po[mt][nt][rr * 2] + p.x,
                                           po[mt][nt][rr * 2 + 1] + p.y);
                    size_t off = (((size_t)b * S_LEN + t0 + mbase + rl) * NH + h) * DIM + col;
                    *reinterpret_cast<float2*>(out + off) = v;
                }
    }
}

extern "C" void kernel_launch(void* const* d_in, const int* in_sizes, int n_in,
                              void* d_out, int out_size) {
    const float* qkv = (const float*)d_in[0];
    float* out = (float*)d_out;
    cudaFuncSetAttribute(ttt_mma_kernel, cudaFuncAttributeMaxDynamicSharedMemorySize,
                         SMEM_TOTAL);
    dim3 grid(32 /*b*h*/, NMB /*reversed T-blocks*/);
    ttt_mma_kernel<<<grid, 128, SMEM_TOTAL>>>(qkv, out);
}